// round 14
// baseline (speedup 1.0000x reference)
#include <cuda_runtime.h>
#include <cuda_fp16.h>
#include <cstdint>

#define T_ 2
#define C_ 64
#define H_ 160
#define W_ 160
#define KS 7
#define K2 49
#define NSPIX 196
#define FAN 3136

#define TH 8
#define TW 16
#define NPIX 128       // TH*TW
#define XR 14          // TH+6
#define XC 22          // TW+6
#define NS 308         // XR*XC
#define HROW 144       // 128B (64 fp16 channels) + 16 pad

// ---- dynamic smem layout (bytes) ----
#define OFF_HALO   0                   // 308*144 = 44352
#define OFF_B      44352               // 3 bufs * 16384 (one k-pair each) = 49152
#define OFF_RW     93504               // 128*49*2 (fp16) = 12544
#define OFF_SCALE  106048              // 128*4 = 512
#define SMEM_MAIN  106560

#define PWD_STRIDE 67
#define PWD_SMEM   (NSPIX*PWD_STRIDE*4 + NSPIX*4)   // 53312

// ---- global scratch ----
__device__ float g_sums[T_*NSPIX*C_];
__device__ float g_cnts[T_*NSPIX];
__device__ float g_pwd[T_*NSPIX*NSPIX];
// per k: 8192B = 64 o-rows of 128B (64 fp16 c-values), XOR-swizzled 16B chunks
__device__ __align__(16) __half g_Wh[K2*C_*C_];

__device__ __forceinline__ int refl(int i, int n){
    if (i < 0) i = -i;
    if (i >= n) i = 2*n - 2 - i;
    return i;
}

__device__ __forceinline__ uint32_t smem_u32(const void* p){
    uint32_t a;
    asm("{ .reg .u64 t; cvta.to.shared.u64 t, %1; cvt.u32.u64 %0, t; }" : "=r"(a) : "l"(p));
    return a;
}

__device__ __forceinline__ void ldsm4(uint32_t* r, uint32_t addr){
    asm volatile("ldmatrix.sync.aligned.m8n8.x4.shared.b16 {%0,%1,%2,%3}, [%4];"
        : "=r"(r[0]), "=r"(r[1]), "=r"(r[2]), "=r"(r[3]) : "r"(addr));
}

__device__ __forceinline__ void mma16816(float* d, const uint32_t* a, const uint32_t* b){
    asm volatile("mma.sync.aligned.m16n8k16.row.col.f32.f16.f16.f32 "
        "{%0,%1,%2,%3}, {%4,%5,%6,%7}, {%8,%9}, {%0,%1,%2,%3};"
        : "+f"(d[0]), "+f"(d[1]), "+f"(d[2]), "+f"(d[3])
        : "r"(a[0]), "r"(a[1]), "r"(a[2]), "r"(a[3]), "r"(b[0]), "r"(b[1]));
}

__device__ __forceinline__ void hmul2(uint32_t& a, uint32_t s){
    asm("mul.rn.f16x2 %0, %0, %1;" : "+r"(a) : "r"(s));
}

__device__ __forceinline__ void cpa16(uint32_t dst, const void* src){
    asm volatile("cp.async.cg.shared.global [%0], [%1], 16;" :: "r"(dst), "l"(src) : "memory");
}
#define CP_COMMIT() asm volatile("cp.async.commit_group;" ::: "memory")
#define CP_WAIT(n)  asm volatile("cp.async.wait_group %0;" :: "n"(n) : "memory")

// ========================= prep kernels =========================

// blocks 0..63: convert W row o=blockIdx to swizzled fp16; rest: zero scratch
__global__ void prep_kernel(const float* __restrict__ W){
    int b = blockIdx.x;
    int tid = threadIdx.x;
    if (b < C_){
        __shared__ float wrow[FAN];
        int o = b;
        for (int i = tid; i < FAN; i += 256) wrow[i] = W[o*FAN + i];
        __syncthreads();
        uint32_t oxor = (uint32_t)((o & 7) << 4);
        char* base = (char*)g_Wh;
        for (int idx = tid; idx < FAN; idx += 256){
            int k = idx >> 6, c = idx & 63;
            __half hv = __float2half_rn(wrow[c*K2 + k]);
            uint32_t boff = (uint32_t)(k*8192 + o*128)
                          + ((((uint32_t)(c>>3))<<4) ^ oxor) + (uint32_t)((c&7)*2);
            *(unsigned short*)(base + boff) = __half_as_ushort(hv);
        }
    } else {
        int i = (b - C_)*256 + tid;
        if (i < T_*NSPIX*C_) g_sums[i] = 0.f;
        if (i < T_*NSPIX)    g_cnts[i] = 0.f;
    }
}

// one warp per pixel: lanes = channels -> coalesced RED
__global__ void accum_kernel(const float* __restrict__ x, const int* __restrict__ spix){
    int tid = threadIdx.x;
    int wi = tid >> 5, l = tid & 31;
    int pix = blockIdx.x*8 + wi;
    if (pix >= T_*H_*W_) return;
    int t = pix / (H_*W_);
    int hw = pix - t*(H_*W_);
    int s = spix[pix];
    const float* xp = x + (size_t)t*C_*H_*W_ + hw;
    float v0 = xp[(size_t)l*(H_*W_)];
    float v1 = xp[(size_t)(l+32)*(H_*W_)];
    float* dst = &g_sums[(t*NSPIX + s)*C_];
    atomicAdd(&dst[l],      v0);
    atomicAdd(&dst[l + 32], v1);
    if (l == 0) atomicAdd(&g_cnts[t*NSPIX + s], 1.0f);
}

// grid T_*49, 256 threads. Coalesced load, stride-67 pad, thread = s, 4 u per block.
__global__ void pwd_kernel(){
    extern __shared__ float sm[];
    float* down = sm;                       // [196][67]
    float* sq   = sm + NSPIX*PWD_STRIDE;
    int t  = blockIdx.x / 49;
    int ub = (blockIdx.x % 49) * 4;
    int tid = threadIdx.x;
    for (int i = tid; i < NSPIX*C_; i += 256){
        int s = i >> 6, c = i & 63;
        float cinv = 1.f / fmaxf(g_cnts[t*NSPIX + s], 1.f);
        down[s*PWD_STRIDE + c] = g_sums[i + t*NSPIX*C_] * cinv;
    }
    __syncthreads();
    if (tid < NSPIX){
        float q = 0.f;
        const float* a = &down[tid*PWD_STRIDE];
        #pragma unroll 8
        for (int c = 0; c < C_; c++) q += a[c]*a[c];
        sq[tid] = q;
    }
    __syncthreads();
    if (tid < NSPIX){
        const float* a = &down[tid*PWD_STRIDE];
        const float* u0 = &down[(ub+0)*PWD_STRIDE];
        const float* u1 = &down[(ub+1)*PWD_STRIDE];
        const float* u2 = &down[(ub+2)*PWD_STRIDE];
        const float* u3 = &down[(ub+3)*PWD_STRIDE];
        float d0=0.f, d1=0.f, d2=0.f, d3=0.f;
        #pragma unroll 8
        for (int c = 0; c < C_; c++){
            float av = a[c];
            d0 += av*u0[c]; d1 += av*u1[c]; d2 += av*u2[c]; d3 += av*u3[c];
        }
        float qs = sq[tid];
        float* dst = &g_pwd[(size_t)(t*NSPIX + tid)*NSPIX + ub];
        dst[0] = fmaxf(qs + sq[ub+0] - 2.f*d0, 0.f);
        dst[1] = fmaxf(qs + sq[ub+1] - 2.f*d1, 0.f);
        dst[2] = fmaxf(qs + sq[ub+2] - 2.f*d2, 0.f);
        dst[3] = fmaxf(qs + sq[ub+3] - 2.f*d3, 0.f);
    }
}

// ========================= main kernel =========================
// 400 CTAs (8x16 px), 256 threads = 8 warps: 4 m-groups x 2 k-parities.
// Each warp: m32 x n64, k = par, par+2, ... ; partial accs merged via smem at end.

__global__ void __launch_bounds__(256, 2) main_kernel(
    const float* __restrict__ x, const int* __restrict__ spix,
    const float* __restrict__ b_lin, const float* __restrict__ w_scale,
    const float* __restrict__ b_scale, float* __restrict__ out)
{
    extern __shared__ char smem[];
    uint32_t sb = smem_u32(smem);
    int tid = threadIdx.x;
    int wi = tid >> 5, l = tid & 31;
    int mi = wi >> 1, par = wi & 1;
    int t = blockIdx.z;
    int gh0 = blockIdx.y*TH, gw0 = blockIdx.x*TW;

    float* scale_s = (float*)(smem + OFF_SCALE);
    __half* rwh    = (__half*)(smem + OFF_RW);

    // ---- phase 1: per-pixel scale ----
    if (tid < NPIX){
        int gh = gh0 + (tid >> 4), gw = gw0 + (tid & 15);
        const float* xp = x + (size_t)t*C_*H_*W_ + gh*W_ + gw;
        float nsq = 0.f, dot = 0.f;
        #pragma unroll 8
        for (int c = 0; c < C_; c++){
            float v = xp[(size_t)c*H_*W_];
            nsq += v*v;
            dot += w_scale[c]*v;
        }
        float z  = dot / (sqrtf(nsq) + 1e-10f) + b_scale[0];
        float sp = fmaxf(z, 0.f) + log1pf(expf(-fabsf(z)));
        scale_s[tid] = 10.f * sp;
    }

    // ---- phase 2: halo load + fp16 convert: row s = [64 fp16][pad16] ----
    for (int i = tid; i < NS*32; i += 256){
        int s  = i >> 5;
        int cp = i & 31;
        int rr = s / XC, cc2 = s - rr*XC;
        int gh = refl(gh0 + rr - 3, H_), gw = refl(gw0 + cc2 - 3, W_);
        const float* xp = x + ((size_t)(t*C_ + 2*cp)*H_ + gh)*W_ + gw;
        float v0 = xp[0], v1 = xp[(size_t)H_*W_];
        __half h0 = __float2half_rn(v0), h1 = __float2half_rn(v1);
        uint32_t uh = (uint32_t)__half_as_ushort(h0) | ((uint32_t)__half_as_ushort(h1) << 16);
        *(uint32_t*)(smem + OFF_HALO + s*HROW + cp*4) = uh;
    }
    __syncthreads();

    // ---- phase 3: rw (stored fp16) ----
    for (int item = tid; item < NPIX*K2; item += 256){
        int p  = item / K2, k = item - p*K2;
        int ki = k / KS,  kj = k - ki*KS;
        int gh = gh0 + (p >> 4), gw = gw0 + (p & 15);
        int rh = refl(gh + ki - 3, H_), rc = refl(gw + kj - 3, W_);
        int sc = spix[(t*H_ + gh)*W_ + gw];
        int nb = spix[(t*H_ + rh)*W_ + rc];
        float v = expf(-scale_s[p] * g_pwd[(size_t)(t*NSPIX + sc)*NSPIX + nb]);
        rwh[item] = __float2half_rn(v);
    }
    __syncthreads();
    if (tid < NPIX){
        float m = 0.f;
        #pragma unroll
        for (int k = 0; k < K2; k++) m = fmaxf(m, __half2float(rwh[tid*K2 + k]));
        float inv = 1.f / (1e-5f + m);
        #pragma unroll
        for (int k = 0; k < K2; k++)
            rwh[tid*K2 + k] = __float2half_rn(__half2float(rwh[tid*K2 + k]) * inv);
    }

    // ---- per-lane static addressing ----
    int rowA = (l & 7) | (((l >> 3) & 1) << 3);   // gw within tile
    int colh = (l >> 4) & 1;
    uint32_t aStat0 = sb + OFF_HALO + (uint32_t)((mi*2*XC + rowA)*HROW) + colh*16;
    uint32_t aStat1 = aStat0 + (uint32_t)(XC*HROW);

    int oRow  = (l & 7) | (((l >> 4) & 1) << 3);
    uint32_t bhalf16 = (uint32_t)(((l >> 3) & 1) << 4);
    uint32_t oxor = (uint32_t)((oRow & 7) << 4);
    uint32_t bRowOff = (uint32_t)(oRow*128);

    int w_lo = l >> 2;                  // gw of acc rows d0,d1
    int p00 = (mi*2*16 + w_lo)*K2;      // tile0 lo rw row
    int p01 = p00 + 8*K2;               // tile0 hi
    int p10 = p00 + 16*K2;              // tile1 lo
    int p11 = p00 + 24*K2;              // tile1 hi

    // ---- preload k-pairs 0 and 1 (16KB each) ----
    #pragma unroll
    for (int pr = 0; pr < 2; pr++){
        const char* src = (const char*)g_Wh + (size_t)pr*16384;
        uint32_t dst = sb + OFF_B + pr*16384;
        #pragma unroll
        for (int j = 0; j < 4; j++){
            int idx = tid + j*256;
            cpa16(dst + idx*16, src + idx*16);
        }
        CP_COMMIT();
    }

    float acc0[32], acc1[32];
    #pragma unroll
    for (int i = 0; i < 32; i++){ acc0[i] = 0.f; acc1[i] = 0.f; }

    // ---- main loop over 25 k-pairs ----
    for (int p = 0; p < 25; p++){
        if (p < 24) CP_WAIT(1); else CP_WAIT(0);
        __syncthreads();                         // pair p visible; pair (p+2)%3 buf free

        if (p + 2 < 25){
            const char* src = (const char*)g_Wh + (size_t)(p+2)*16384;
            uint32_t dst = sb + OFF_B + ((p+2)%3)*16384;
            int jmax = (p+2 == 24) ? 2 : 4;      // pair 24 has only k=48
            for (int j = 0; j < jmax; j++){
                int idx = tid + j*256;
                cpa16(dst + idx*16, src + idx*16);
            }
            CP_COMMIT();
        }

        int k = 2*p + par;
        if (k < K2){
            uint32_t bBase = sb + OFF_B + (p%3)*16384 + par*8192;
            int ki = k / KS, kj = k - ki*KS;
            uint32_t koff = (uint32_t)((ki*XC + kj)*HROW);
            uint32_t aA0 = aStat0 + koff;
            uint32_t aA1 = aStat1 + koff;

            uint32_t s00, s01, s10, s11;
            {
                uint32_t u;
                u = (uint32_t)__half_as_ushort(rwh[p00 + k]); s00 = u | (u<<16);
                u = (uint32_t)__half_as_ushort(rwh[p01 + k]); s01 = u | (u<<16);
                u = (uint32_t)__half_as_ushort(rwh[p10 + k]); s10 = u | (u<<16);
                u = (uint32_t)__half_as_ushort(rwh[p11 + k]); s11 = u | (u<<16);
            }

            #pragma unroll
            for (int kc = 0; kc < 4; kc++){
                uint32_t a0[4], a1[4];
                ldsm4(a0, aA0 + kc*32);
                ldsm4(a1, aA1 + kc*32);
                hmul2(a0[0], s00); hmul2(a0[2], s00);
                hmul2(a0[1], s01); hmul2(a0[3], s01);
                hmul2(a1[0], s10); hmul2(a1[2], s10);
                hmul2(a1[1], s11); hmul2(a1[3], s11);

                uint32_t bA = bBase + bRowOff + (((uint32_t)(kc*32) + bhalf16) ^ oxor);
                uint32_t b0[4], b1[4], b2[4], b3[4];
                ldsm4(b0, bA);
                ldsm4(b1, bA + 2048);
                ldsm4(b2, bA + 4096);
                ldsm4(b3, bA + 6144);

                mma16816(&acc0[0],  a0, b0);   mma16816(&acc0[4],  a0, b0+2);
                mma16816(&acc0[8],  a0, b1);   mma16816(&acc0[12], a0, b1+2);
                mma16816(&acc0[16], a0, b2);   mma16816(&acc0[20], a0, b2+2);
                mma16816(&acc0[24], a0, b3);   mma16816(&acc0[28], a0, b3+2);
                mma16816(&acc1[0],  a1, b0);   mma16816(&acc1[4],  a1, b0+2);
                mma16816(&acc1[8],  a1, b1);   mma16816(&acc1[12], a1, b1+2);
                mma16816(&acc1[16], a1, b2);   mma16816(&acc1[20], a1, b2+2);
                mma16816(&acc1[24], a1, b3);   mma16816(&acc1[28], a1, b3+2);
            }
        }
    }

    // ---- cross-parity reduction via smem, then store ----
    __syncthreads();                    // all compute done; B region reusable
    float* red = (float*)(smem + OFF_B) + mi*2048;
    if (par == 1){
        #pragma unroll
        for (int i = 0; i < 32; i++){
            red[i*32 + l]        = acc0[i];
            red[(i+32)*32 + l]   = acc1[i];
        }
    }
    __syncthreads();
    if (par == 0){
        #pragma unroll
        for (int i = 0; i < 32; i++){
            acc0[i] += red[i*32 + l];
            acc1[i] += red[(i+32)*32 + l];
        }
        #pragma unroll
        for (int tt = 0; tt < 2; tt++){
            float* a = tt ? acc1 : acc0;
            int gh = gh0 + mi*2 + tt;
            int gwl = gw0 + w_lo;
            int gwh = gwl + 8;
            #pragma unroll
            for (int g = 0; g < 8; g++){
                int o = g*8 + 2*(l & 3);
                float b0 = b_lin[o], b1 = b_lin[o+1];
                out[((size_t)(t*C_ + o  )*H_ + gh)*W_ + gwl] = a[g*4 + 0] + b0;
                out[((size_t)(t*C_ + o+1)*H_ + gh)*W_ + gwl] = a[g*4 + 1] + b1;
                out[((size_t)(t*C_ + o  )*H_ + gh)*W_ + gwh] = a[g*4 + 2] + b0;
                out[((size_t)(t*C_ + o+1)*H_ + gh)*W_ + gwh] = a[g*4 + 3] + b1;
            }
        }
    }
}

// ========================= launch =========================

extern "C" void kernel_launch(void* const* d_in, const int* in_sizes, int n_in,
                              void* d_out, int out_size)
{
    const float* x       = (const float*)d_in[0];
    const int*   spix    = (const int*)  d_in[1];
    const float* W       = (const float*)d_in[2];
    const float* b_lin   = (const float*)d_in[3];
    const float* w_scale = (const float*)d_in[4];
    const float* b_scale = (const float*)d_in[5];
    float* out = (float*)d_out;

    cudaFuncSetAttribute(pwd_kernel,  cudaFuncAttributeMaxDynamicSharedMemorySize, PWD_SMEM);
    cudaFuncSetAttribute(main_kernel, cudaFuncAttributeMaxDynamicSharedMemorySize, SMEM_MAIN);

    prep_kernel  <<<C_ + (T_*NSPIX*C_ + 255)/256, 256>>>(W);
    accum_kernel <<<(T_*H_*W_ + 7)/8, 256>>>(x, spix);
    pwd_kernel   <<<T_*49, 256, PWD_SMEM>>>();

    dim3 grid(W_/TW, H_/TH, T_);
    main_kernel<<<grid, 256, SMEM_MAIN>>>(x, spix, b_lin, w_scale, b_scale, out);
}

// round 15
// speedup vs baseline: 1.0555x; 1.0555x over previous
#include <cuda_runtime.h>
#include <cuda_fp16.h>
#include <cstdint>

#define T_ 2
#define C_ 64
#define H_ 160
#define W_ 160
#define KS 7
#define K2 49
#define NSPIX 196
#define FAN 3136

#define TH 8
#define TW 16
#define NPIX 128       // TH*TW
#define XR 14          // TH+6
#define XC 22          // TW+6
#define NS 308         // XR*XC
#define HROW 144       // 128B (64 fp16 channels) + 16 pad

// ---- dynamic smem layout (bytes) ----
#define OFF_HALO   0                   // 308*144 = 44352
#define OFF_B      44352               // 3 bufs * 8192 = 24576
#define OFF_RW     68928               // 128*49*4 = 25088
#define OFF_SCALE  94016               // 128*4 = 512
#define SMEM_MAIN  94528

#define PWD_STRIDE 67
#define PWD_SMEM   (NSPIX*PWD_STRIDE*4 + NSPIX*4)   // 53312

// ---- global scratch ----
__device__ float g_sums[T_*NSPIX*C_];
__device__ float g_cnts[T_*NSPIX];
__device__ float g_pwd[T_*NSPIX*NSPIX];
// per k: 8192B = 64 o-rows of 128B (64 fp16 c-values), XOR-swizzled 16B chunks
__device__ __align__(16) __half g_Wh[K2*C_*C_];

__device__ __forceinline__ int refl(int i, int n){
    if (i < 0) i = -i;
    if (i >= n) i = 2*n - 2 - i;
    return i;
}

__device__ __forceinline__ uint32_t smem_u32(const void* p){
    uint32_t a;
    asm("{ .reg .u64 t; cvta.to.shared.u64 t, %1; cvt.u32.u64 %0, t; }" : "=r"(a) : "l"(p));
    return a;
}

__device__ __forceinline__ void ldsm4(uint32_t* r, uint32_t addr){
    asm volatile("ldmatrix.sync.aligned.m8n8.x4.shared.b16 {%0,%1,%2,%3}, [%4];"
        : "=r"(r[0]), "=r"(r[1]), "=r"(r[2]), "=r"(r[3]) : "r"(addr));
}

__device__ __forceinline__ void mma16816(float* d, const uint32_t* a, const uint32_t* b){
    asm volatile("mma.sync.aligned.m16n8k16.row.col.f32.f16.f16.f32 "
        "{%0,%1,%2,%3}, {%4,%5,%6,%7}, {%8,%9}, {%0,%1,%2,%3};"
        : "+f"(d[0]), "+f"(d[1]), "+f"(d[2]), "+f"(d[3])
        : "r"(a[0]), "r"(a[1]), "r"(a[2]), "r"(a[3]), "r"(b[0]), "r"(b[1]));
}

__device__ __forceinline__ void hmul2(uint32_t& a, uint32_t s){
    asm("mul.rn.f16x2 %0, %0, %1;" : "+r"(a) : "r"(s));
}

__device__ __forceinline__ void cpa16(uint32_t dst, const void* src){
    asm volatile("cp.async.cg.shared.global [%0], [%1], 16;" :: "r"(dst), "l"(src) : "memory");
}
#define CP_COMMIT() asm volatile("cp.async.commit_group;" ::: "memory")
#define CP_WAIT(n)  asm volatile("cp.async.wait_group %0;" :: "n"(n) : "memory")

// ========================= prep kernels =========================

// blocks 0..63: convert W row o=blockIdx to swizzled fp16; rest: zero scratch
__global__ void prep_kernel(const float* __restrict__ W){
    int b = blockIdx.x;
    int tid = threadIdx.x;
    if (b < C_){
        __shared__ float wrow[FAN];
        int o = b;
        for (int i = tid; i < FAN; i += 256) wrow[i] = W[o*FAN + i];
        __syncthreads();
        uint32_t oxor = (uint32_t)((o & 7) << 4);
        char* base = (char*)g_Wh;
        for (int idx = tid; idx < FAN; idx += 256){
            int k = idx >> 6, c = idx & 63;
            __half hv = __float2half_rn(wrow[c*K2 + k]);
            uint32_t boff = (uint32_t)(k*8192 + o*128)
                          + ((((uint32_t)(c>>3))<<4) ^ oxor) + (uint32_t)((c&7)*2);
            *(unsigned short*)(base + boff) = __half_as_ushort(hv);
        }
    } else {
        int i = (b - C_)*256 + tid;
        if (i < T_*NSPIX*C_) g_sums[i] = 0.f;
        if (i < T_*NSPIX)    g_cnts[i] = 0.f;
    }
}

// one warp per pixel: lanes = channels -> coalesced RED
__global__ void accum_kernel(const float* __restrict__ x, const int* __restrict__ spix){
    int tid = threadIdx.x;
    int wi = tid >> 5, l = tid & 31;
    int pix = blockIdx.x*8 + wi;
    if (pix >= T_*H_*W_) return;
    int t = pix / (H_*W_);
    int hw = pix - t*(H_*W_);
    int s = spix[pix];
    const float* xp = x + (size_t)t*C_*H_*W_ + hw;
    float v0 = xp[(size_t)l*(H_*W_)];
    float v1 = xp[(size_t)(l+32)*(H_*W_)];
    float* dst = &g_sums[(t*NSPIX + s)*C_];
    atomicAdd(&dst[l],      v0);
    atomicAdd(&dst[l + 32], v1);
    if (l == 0) atomicAdd(&g_cnts[t*NSPIX + s], 1.0f);
}

// grid T_*49, 256 threads. Coalesced load, stride-67 pad, thread = s, 4 u per block.
__global__ void pwd_kernel(){
    extern __shared__ float sm[];
    float* down = sm;                       // [196][67]
    float* sq   = sm + NSPIX*PWD_STRIDE;
    int t  = blockIdx.x / 49;
    int ub = (blockIdx.x % 49) * 4;
    int tid = threadIdx.x;
    for (int i = tid; i < NSPIX*C_; i += 256){
        int s = i >> 6, c = i & 63;
        float cinv = 1.f / fmaxf(g_cnts[t*NSPIX + s], 1.f);
        down[s*PWD_STRIDE + c] = g_sums[i + t*NSPIX*C_] * cinv;
    }
    __syncthreads();
    if (tid < NSPIX){
        float q = 0.f;
        const float* a = &down[tid*PWD_STRIDE];
        #pragma unroll 8
        for (int c = 0; c < C_; c++) q += a[c]*a[c];
        sq[tid] = q;
    }
    __syncthreads();
    if (tid < NSPIX){
        const float* a = &down[tid*PWD_STRIDE];
        const float* u0 = &down[(ub+0)*PWD_STRIDE];
        const float* u1 = &down[(ub+1)*PWD_STRIDE];
        const float* u2 = &down[(ub+2)*PWD_STRIDE];
        const float* u3 = &down[(ub+3)*PWD_STRIDE];
        float d0=0.f, d1=0.f, d2=0.f, d3=0.f;
        #pragma unroll 8
        for (int c = 0; c < C_; c++){
            float av = a[c];
            d0 += av*u0[c]; d1 += av*u1[c]; d2 += av*u2[c]; d3 += av*u3[c];
        }
        float qs = sq[tid];
        float* dst = &g_pwd[(size_t)(t*NSPIX + tid)*NSPIX + ub];
        dst[0] = fmaxf(qs + sq[ub+0] - 2.f*d0, 0.f);
        dst[1] = fmaxf(qs + sq[ub+1] - 2.f*d1, 0.f);
        dst[2] = fmaxf(qs + sq[ub+2] - 2.f*d2, 0.f);
        dst[3] = fmaxf(qs + sq[ub+3] - 2.f*d3, 0.f);
    }
}

// ========================= main kernel =========================
// 400 CTAs (8x16 px), 256 threads (8 warps: 4m x 2n, warp tile m32 x n32), occ 2.
// 1-pass fp16, rw folded into A fragments, 3-buffer cp.async, ONE barrier per k.

__global__ void __launch_bounds__(256, 2) main_kernel(
    const float* __restrict__ x, const int* __restrict__ spix,
    const float* __restrict__ b_lin, const float* __restrict__ w_scale,
    const float* __restrict__ b_scale, float* __restrict__ out)
{
    extern __shared__ char smem[];
    uint32_t sb = smem_u32(smem);
    int tid = threadIdx.x;
    int wi = tid >> 5, l = tid & 31;
    int mi = wi >> 1, ni = wi & 1;
    int t = blockIdx.z;
    int gh0 = blockIdx.y*TH, gw0 = blockIdx.x*TW;

    float* scale_s = (float*)(smem + OFF_SCALE);
    float* rw      = (float*)(smem + OFF_RW);

    // ---- phase 1: per-pixel scale ----
    if (tid < NPIX){
        int gh = gh0 + (tid >> 4), gw = gw0 + (tid & 15);
        const float* xp = x + (size_t)t*C_*H_*W_ + gh*W_ + gw;
        float nsq = 0.f, dot = 0.f;
        #pragma unroll 8
        for (int c = 0; c < C_; c++){
            float v = xp[(size_t)c*H_*W_];
            nsq += v*v;
            dot += w_scale[c]*v;
        }
        float z  = dot / (sqrtf(nsq) + 1e-10f) + b_scale[0];
        float sp = fmaxf(z, 0.f) + log1pf(expf(-fabsf(z)));
        scale_s[tid] = 10.f * sp;
    }

    // ---- phase 2: halo load + fp16 convert: row s = [64 fp16][pad16] ----
    for (int i = tid; i < NS*32; i += 256){
        int s  = i >> 5;
        int cp = i & 31;          // channel pair
        int rr = s / XC, cc2 = s - rr*XC;
        int gh = refl(gh0 + rr - 3, H_), gw = refl(gw0 + cc2 - 3, W_);
        const float* xp = x + ((size_t)(t*C_ + 2*cp)*H_ + gh)*W_ + gw;
        float v0 = xp[0], v1 = xp[(size_t)H_*W_];
        __half h0 = __float2half_rn(v0), h1 = __float2half_rn(v1);
        uint32_t uh = (uint32_t)__half_as_ushort(h0) | ((uint32_t)__half_as_ushort(h1) << 16);
        *(uint32_t*)(smem + OFF_HALO + s*HROW + cp*4) = uh;
    }
    __syncthreads();

    // ---- phase 3: rw ----
    for (int item = tid; item < NPIX*K2; item += 256){
        int p  = item / K2, k = item - p*K2;
        int ki = k / KS,  kj = k - ki*KS;
        int gh = gh0 + (p >> 4), gw = gw0 + (p & 15);
        int rh = refl(gh + ki - 3, H_), rc = refl(gw + kj - 3, W_);
        int sc = spix[(t*H_ + gh)*W_ + gw];
        int nb = spix[(t*H_ + rh)*W_ + rc];
        rw[item] = expf(-scale_s[p] * g_pwd[(size_t)(t*NSPIX + sc)*NSPIX + nb]);
    }
    __syncthreads();
    if (tid < NPIX){
        float m = 0.f;
        #pragma unroll
        for (int k = 0; k < K2; k++) m = fmaxf(m, rw[tid*K2 + k]);
        float inv = 1.f / (1e-5f + m);
        #pragma unroll
        for (int k = 0; k < K2; k++) rw[tid*K2 + k] *= inv;
    }

    // ---- per-lane static addressing ----
    int rowA = (l & 7) | (((l >> 3) & 1) << 3);   // gw within tile
    int colh = (l >> 4) & 1;
    int tb0 = mi*2, tb1 = mi*2 + 1;
    uint32_t aStat0 = sb + OFF_HALO + (uint32_t)((tb0*XC + rowA)*HROW) + colh*16;
    uint32_t aStat1 = sb + OFF_HALO + (uint32_t)((tb1*XC + rowA)*HROW) + colh*16;

    int oRow  = (l & 7) | (((l >> 4) & 1) << 3);
    uint32_t bhalf16 = (uint32_t)(((l >> 3) & 1) << 4);
    int o0 = ni*32 + oRow;
    int o1 = o0 + 16;
    uint32_t bOff0 = (uint32_t)(o0*128), bXor0 = (uint32_t)((o0 & 7) << 4);
    uint32_t bOff1 = (uint32_t)(o1*128), bXor1 = (uint32_t)((o1 & 7) << 4);

    // rw rows for my accumulators
    int w_lo = l >> 2;                 // d0,d1 row (w pos in tile)
    int p00 = (tb0*16 + w_lo)*K2;      // tile0 lo
    int p01 = p00 + 8*K2;              // tile0 hi
    int p10 = (tb1*16 + w_lo)*K2;
    int p11 = p10 + 8*K2;

    // ---- preload B for k=0 and k=1 (8KB each: 512 x 16B, 2 per thread) ----
    #pragma unroll
    for (int pk = 0; pk < 2; pk++){
        const char* src = (const char*)g_Wh + (size_t)pk*8192;
        uint32_t dst = sb + OFF_B + pk*8192;
        cpa16(dst + tid*16,       src + tid*16);
        cpa16(dst + (tid+256)*16, src + (tid+256)*16);
        CP_COMMIT();
    }

    float acc0[16], acc1[16];
    #pragma unroll
    for (int i = 0; i < 16; i++){ acc0[i] = 0.f; acc1[i] = 0.f; }

    // ---- main loop over 49 kernel offsets (3-buffer, one barrier per k) ----
    int kj = 0;
    uint32_t koff = 0;
    for (int k = 0; k < K2; k++){
        if (k < K2-1) CP_WAIT(1); else CP_WAIT(0);
        __syncthreads();   // buf k%3 visible to all; buf (k+2)%3 readers (iter k-1) done

        if (k + 2 < K2){
            const char* src = (const char*)g_Wh + (size_t)(k+2)*8192;
            uint32_t dst = sb + OFF_B + ((k+2)%3)*8192;
            cpa16(dst + tid*16,       src + tid*16);
            cpa16(dst + (tid+256)*16, src + (tid+256)*16);
            CP_COMMIT();
        }

        uint32_t bBase = sb + OFF_B + (k%3)*8192;
        uint32_t aA0 = aStat0 + koff;
        uint32_t aA1 = aStat1 + koff;

        // rw scales for this k as f16x2 (same value in both halves)
        uint32_t s00, s01, s10, s11;
        {
            __half2 h;
            h = __floats2half2_rn(rw[p00 + k], rw[p00 + k]); s00 = *(uint32_t*)&h;
            h = __floats2half2_rn(rw[p01 + k], rw[p01 + k]); s01 = *(uint32_t*)&h;
            h = __floats2half2_rn(rw[p10 + k], rw[p10 + k]); s10 = *(uint32_t*)&h;
            h = __floats2half2_rn(rw[p11 + k], rw[p11 + k]); s11 = *(uint32_t*)&h;
        }

        #pragma unroll
        for (int kc = 0; kc < 4; kc++){
            uint32_t a0[4], a1[4];
            ldsm4(a0, aA0 + kc*32);
            ldsm4(a1, aA1 + kc*32);
            // fold rw into A: regs 0,2 = row l/4 (lo); regs 1,3 = row l/4+8 (hi)
            hmul2(a0[0], s00); hmul2(a0[2], s00);
            hmul2(a0[1], s01); hmul2(a0[3], s01);
            hmul2(a1[0], s10); hmul2(a1[2], s10);
            hmul2(a1[1], s11); hmul2(a1[3], s11);

            uint32_t csw = (uint32_t)(kc*32) + bhalf16;
            uint32_t b0[4], b1[4];
            ldsm4(b0, bBase + bOff0 + (csw ^ bXor0));
            ldsm4(b1, bBase + bOff1 + (csw ^ bXor1));

            mma16816(&acc0[0],  a0, b0);
            mma16816(&acc0[4],  a0, b0+2);
            mma16816(&acc0[8],  a0, b1);
            mma16816(&acc0[12], a0, b1+2);
            mma16816(&acc1[0],  a1, b0);
            mma16816(&acc1[4],  a1, b0+2);
            mma16816(&acc1[8],  a1, b1);
            mma16816(&acc1[12], a1, b1+2);
        }

        // advance k -> k+1 offset without division
        kj++; koff += HROW;
        if (kj == KS){ kj = 0; koff += (uint32_t)((XC - KS)*HROW); }
    }

    // ---- store ----
    #pragma unroll
    for (int tt = 0; tt < 2; tt++){
        float* a = tt ? acc1 : acc0;
        int gh = gh0 + mi*2 + tt;
        int gwl = gw0 + w_lo;
        int gwh = gwl + 8;
        #pragma unroll
        for (int g = 0; g < 4; g++){
            int o = ni*32 + g*8 + 2*(l & 3);
            float b0 = b_lin[o], b1 = b_lin[o+1];
            out[((size_t)(t*C_ + o  )*H_ + gh)*W_ + gwl] = a[g*4 + 0] + b0;
            out[((size_t)(t*C_ + o+1)*H_ + gh)*W_ + gwl] = a[g*4 + 1] + b1;
            out[((size_t)(t*C_ + o  )*H_ + gh)*W_ + gwh] = a[g*4 + 2] + b0;
            out[((size_t)(t*C_ + o+1)*H_ + gh)*W_ + gwh] = a[g*4 + 3] + b1;
        }
    }
}

// ========================= launch =========================

extern "C" void kernel_launch(void* const* d_in, const int* in_sizes, int n_in,
                              void* d_out, int out_size)
{
    const float* x       = (const float*)d_in[0];
    const int*   spix    = (const int*)  d_in[1];
    const float* W       = (const float*)d_in[2];
    const float* b_lin   = (const float*)d_in[3];
    const float* w_scale = (const float*)d_in[4];
    const float* b_scale = (const float*)d_in[5];
    float* out = (float*)d_out;

    cudaFuncSetAttribute(pwd_kernel,  cudaFuncAttributeMaxDynamicSharedMemorySize, PWD_SMEM);
    cudaFuncSetAttribute(main_kernel, cudaFuncAttributeMaxDynamicSharedMemorySize, SMEM_MAIN);

    prep_kernel  <<<C_ + (T_*NSPIX*C_ + 255)/256, 256>>>(W);
    accum_kernel <<<(T_*H_*W_ + 7)/8, 256>>>(x, spix);
    pwd_kernel   <<<T_*49, 256, PWD_SMEM>>>();

    dim3 grid(W_/TW, H_/TH, T_);
    main_kernel<<<grid, 256, SMEM_MAIN>>>(x, spix, b_lin, w_scale, b_scale, out);
}

// round 16
// speedup vs baseline: 1.0649x; 1.0089x over previous
#include <cuda_runtime.h>
#include <cuda_fp16.h>
#include <cstdint>

#define T_ 2
#define C_ 64
#define H_ 160
#define W_ 160
#define KS 7
#define K2 49
#define NSPIX 196
#define FAN 3136

#define TH 8
#define TW 16
#define NPIX 128       // TH*TW
#define XR 14          // TH+6
#define XC 22          // TW+6
#define NS 308         // XR*XC
#define HROW 144       // 128B (64 fp16 channels) + 16 pad

// ---- dynamic smem layout (bytes) ----
#define OFF_HALO   0                   // 308*144 = 44352
#define OFF_B      44352               // 3 bufs * 8192 = 24576
#define OFF_RW     68928               // 128*49*4 = 25088 (f16x2-packed u32 after phase 3)
#define OFF_SCALE  94016               // 128*4 = 512
#define SMEM_MAIN  94528

#define PWD_STRIDE 67
#define PWD_SMEM   (NSPIX*PWD_STRIDE*4 + NSPIX*4)   // 53312

// ---- global scratch ----
__device__ float g_sums[T_*NSPIX*C_];
__device__ float g_cnts[T_*NSPIX];
__device__ float g_pwd[T_*NSPIX*NSPIX];
// per k: 8192B = 64 o-rows of 128B (64 fp16 c-values), XOR-swizzled 16B chunks
__device__ __align__(16) __half g_Wh[K2*C_*C_];

__device__ __forceinline__ int refl(int i, int n){
    if (i < 0) i = -i;
    if (i >= n) i = 2*n - 2 - i;
    return i;
}

__device__ __forceinline__ uint32_t smem_u32(const void* p){
    uint32_t a;
    asm("{ .reg .u64 t; cvta.to.shared.u64 t, %1; cvt.u32.u64 %0, t; }" : "=r"(a) : "l"(p));
    return a;
}

__device__ __forceinline__ void ldsm4(uint32_t* r, uint32_t addr){
    asm volatile("ldmatrix.sync.aligned.m8n8.x4.shared.b16 {%0,%1,%2,%3}, [%4];"
        : "=r"(r[0]), "=r"(r[1]), "=r"(r[2]), "=r"(r[3]) : "r"(addr));
}

__device__ __forceinline__ void mma16816(float* d, const uint32_t* a, const uint32_t* b){
    asm volatile("mma.sync.aligned.m16n8k16.row.col.f32.f16.f16.f32 "
        "{%0,%1,%2,%3}, {%4,%5,%6,%7}, {%8,%9}, {%0,%1,%2,%3};"
        : "+f"(d[0]), "+f"(d[1]), "+f"(d[2]), "+f"(d[3])
        : "r"(a[0]), "r"(a[1]), "r"(a[2]), "r"(a[3]), "r"(b[0]), "r"(b[1]));
}

__device__ __forceinline__ void hmul2(uint32_t& a, uint32_t s){
    asm("mul.rn.f16x2 %0, %0, %1;" : "+r"(a) : "r"(s));
}

__device__ __forceinline__ void cpa16(uint32_t dst, const void* src){
    asm volatile("cp.async.cg.shared.global [%0], [%1], 16;" :: "r"(dst), "l"(src) : "memory");
}
#define CP_COMMIT() asm volatile("cp.async.commit_group;" ::: "memory")
#define CP_WAIT(n)  asm volatile("cp.async.wait_group %0;" :: "n"(n) : "memory")

// ========================= prep kernels =========================

// blocks 0..63: convert W row o=blockIdx to swizzled fp16; rest: zero scratch
__global__ void prep_kernel(const float* __restrict__ W){
    int b = blockIdx.x;
    int tid = threadIdx.x;
    if (b < C_){
        __shared__ float wrow[FAN];
        int o = b;
        for (int i = tid; i < FAN; i += 256) wrow[i] = W[o*FAN + i];
        __syncthreads();
        uint32_t oxor = (uint32_t)((o & 7) << 4);
        char* base = (char*)g_Wh;
        for (int idx = tid; idx < FAN; idx += 256){
            int k = idx >> 6, c = idx & 63;
            __half hv = __float2half_rn(wrow[c*K2 + k]);
            uint32_t boff = (uint32_t)(k*8192 + o*128)
                          + ((((uint32_t)(c>>3))<<4) ^ oxor) + (uint32_t)((c&7)*2);
            *(unsigned short*)(base + boff) = __half_as_ushort(hv);
        }
    } else {
        int i = (b - C_)*256 + tid;
        if (i < T_*NSPIX*C_) g_sums[i] = 0.f;
        if (i < T_*NSPIX)    g_cnts[i] = 0.f;
    }
}

// one warp per pixel: lanes = channels -> coalesced RED
__global__ void accum_kernel(const float* __restrict__ x, const int* __restrict__ spix){
    int tid = threadIdx.x;
    int wi = tid >> 5, l = tid & 31;
    int pix = blockIdx.x*8 + wi;
    if (pix >= T_*H_*W_) return;
    int t = pix / (H_*W_);
    int hw = pix - t*(H_*W_);
    int s = spix[pix];
    const float* xp = x + (size_t)t*C_*H_*W_ + hw;
    float v0 = xp[(size_t)l*(H_*W_)];
    float v1 = xp[(size_t)(l+32)*(H_*W_)];
    float* dst = &g_sums[(t*NSPIX + s)*C_];
    atomicAdd(&dst[l],      v0);
    atomicAdd(&dst[l + 32], v1);
    if (l == 0) atomicAdd(&g_cnts[t*NSPIX + s], 1.0f);
}

// grid T_*49, 256 threads. Coalesced load, stride-67 pad, thread = s, 4 u per block.
__global__ void pwd_kernel(){
    extern __shared__ float sm[];
    float* down = sm;                       // [196][67]
    float* sq   = sm + NSPIX*PWD_STRIDE;
    int t  = blockIdx.x / 49;
    int ub = (blockIdx.x % 49) * 4;
    int tid = threadIdx.x;
    for (int i = tid; i < NSPIX*C_; i += 256){
        int s = i >> 6, c = i & 63;
        float cinv = 1.f / fmaxf(g_cnts[t*NSPIX + s], 1.f);
        down[s*PWD_STRIDE + c] = g_sums[i + t*NSPIX*C_] * cinv;
    }
    __syncthreads();
    if (tid < NSPIX){
        float q = 0.f;
        const float* a = &down[tid*PWD_STRIDE];
        #pragma unroll 8
        for (int c = 0; c < C_; c++) q += a[c]*a[c];
        sq[tid] = q;
    }
    __syncthreads();
    if (tid < NSPIX){
        const float* a = &down[tid*PWD_STRIDE];
        const float* u0 = &down[(ub+0)*PWD_STRIDE];
        const float* u1 = &down[(ub+1)*PWD_STRIDE];
        const float* u2 = &down[(ub+2)*PWD_STRIDE];
        const float* u3 = &down[(ub+3)*PWD_STRIDE];
        float d0=0.f, d1=0.f, d2=0.f, d3=0.f;
        #pragma unroll 8
        for (int c = 0; c < C_; c++){
            float av = a[c];
            d0 += av*u0[c]; d1 += av*u1[c]; d2 += av*u2[c]; d3 += av*u3[c];
        }
        float qs = sq[tid];
        float* dst = &g_pwd[(size_t)(t*NSPIX + tid)*NSPIX + ub];
        dst[0] = fmaxf(qs + sq[ub+0] - 2.f*d0, 0.f);
        dst[1] = fmaxf(qs + sq[ub+1] - 2.f*d1, 0.f);
        dst[2] = fmaxf(qs + sq[ub+2] - 2.f*d2, 0.f);
        dst[3] = fmaxf(qs + sq[ub+3] - 2.f*d3, 0.f);
    }
}

// ========================= main kernel =========================
// 400 CTAs (8x16 px), 256 threads (8 warps: 4m x 2n, warp tile m32 x n32), occ 2.
// 1-pass fp16, rw folded into A (pre-packed f16x2), fragment double-buffer across kc.

__global__ void __launch_bounds__(256, 2) main_kernel(
    const float* __restrict__ x, const int* __restrict__ spix,
    const float* __restrict__ b_lin, const float* __restrict__ w_scale,
    const float* __restrict__ b_scale, float* __restrict__ out)
{
    extern __shared__ char smem[];
    uint32_t sb = smem_u32(smem);
    int tid = threadIdx.x;
    int wi = tid >> 5, l = tid & 31;
    int mi = wi >> 1, ni = wi & 1;
    int t = blockIdx.z;
    int gh0 = blockIdx.y*TH, gw0 = blockIdx.x*TW;

    float* scale_s = (float*)(smem + OFF_SCALE);
    float* rw      = (float*)(smem + OFF_RW);

    // ---- phase 1: per-pixel scale ----
    if (tid < NPIX){
        int gh = gh0 + (tid >> 4), gw = gw0 + (tid & 15);
        const float* xp = x + (size_t)t*C_*H_*W_ + gh*W_ + gw;
        float nsq = 0.f, dot = 0.f;
        #pragma unroll 8
        for (int c = 0; c < C_; c++){
            float v = xp[(size_t)c*H_*W_];
            nsq += v*v;
            dot += w_scale[c]*v;
        }
        float z  = dot / (sqrtf(nsq) + 1e-10f) + b_scale[0];
        float sp = fmaxf(z, 0.f) + log1pf(expf(-fabsf(z)));
        scale_s[tid] = 10.f * sp;
    }

    // ---- phase 2: halo load + fp16 convert: row s = [64 fp16][pad16] ----
    for (int i = tid; i < NS*32; i += 256){
        int s  = i >> 5;
        int cp = i & 31;          // channel pair
        int rr = s / XC, cc2 = s - rr*XC;
        int gh = refl(gh0 + rr - 3, H_), gw = refl(gw0 + cc2 - 3, W_);
        const float* xp = x + ((size_t)(t*C_ + 2*cp)*H_ + gh)*W_ + gw;
        float v0 = xp[0], v1 = xp[(size_t)H_*W_];
        __half h0 = __float2half_rn(v0), h1 = __float2half_rn(v1);
        uint32_t uh = (uint32_t)__half_as_ushort(h0) | ((uint32_t)__half_as_ushort(h1) << 16);
        *(uint32_t*)(smem + OFF_HALO + s*HROW + cp*4) = uh;
    }
    __syncthreads();

    // ---- phase 3: rw (fp32), then normalize + pack to duplicated f16x2 in-place ----
    for (int item = tid; item < NPIX*K2; item += 256){
        int p  = item / K2, k = item - p*K2;
        int ki = k / KS,  kj = k - ki*KS;
        int gh = gh0 + (p >> 4), gw = gw0 + (p & 15);
        int rh = refl(gh + ki - 3, H_), rc = refl(gw + kj - 3, W_);
        int sc = spix[(t*H_ + gh)*W_ + gw];
        int nb = spix[(t*H_ + rh)*W_ + rc];
        rw[item] = expf(-scale_s[p] * g_pwd[(size_t)(t*NSPIX + sc)*NSPIX + nb]);
    }
    __syncthreads();
    if (tid < NPIX){
        float m = 0.f;
        #pragma unroll
        for (int k = 0; k < K2; k++) m = fmaxf(m, rw[tid*K2 + k]);
        float inv = 1.f / (1e-5f + m);
        #pragma unroll
        for (int k = 0; k < K2; k++){
            float f = rw[tid*K2 + k] * inv;
            __half2 h = __floats2half2_rn(f, f);
            ((uint32_t*)rw)[tid*K2 + k] = *(uint32_t*)&h;
        }
    }

    // ---- per-lane static addressing ----
    int rowA = (l & 7) | (((l >> 3) & 1) << 3);   // gw within tile
    int colh = (l >> 4) & 1;
    int tb0 = mi*2, tb1 = mi*2 + 1;
    uint32_t aStat0 = sb + OFF_HALO + (uint32_t)((tb0*XC + rowA)*HROW) + colh*16;
    uint32_t aStat1 = sb + OFF_HALO + (uint32_t)((tb1*XC + rowA)*HROW) + colh*16;

    int oRow  = (l & 7) | (((l >> 4) & 1) << 3);
    uint32_t bhalf16 = (uint32_t)(((l >> 3) & 1) << 4);
    int o0 = ni*32 + oRow;
    int o1 = o0 + 16;
    uint32_t bOff0 = (uint32_t)(o0*128), bXor0 = (uint32_t)((o0 & 7) << 4);
    uint32_t bOff1 = (uint32_t)(o1*128), bXor1 = (uint32_t)((o1 & 7) << 4);

    // rw rows for my accumulators
    int w_lo = l >> 2;                 // d0,d1 row (w pos in tile)
    int p00 = (tb0*16 + w_lo)*K2;      // tile0 lo
    int p01 = p00 + 8*K2;              // tile0 hi
    int p10 = (tb1*16 + w_lo)*K2;
    int p11 = p10 + 8*K2;
    const uint32_t* rwp = (const uint32_t*)rw;

    // ---- preload B for k=0 and k=1 (8KB each: 512 x 16B, 2 per thread) ----
    #pragma unroll
    for (int pk = 0; pk < 2; pk++){
        const char* src = (const char*)g_Wh + (size_t)pk*8192;
        uint32_t dst = sb + OFF_B + pk*8192;
        cpa16(dst + tid*16,       src + tid*16);
        cpa16(dst + (tid+256)*16, src + (tid+256)*16);
        CP_COMMIT();
    }

    float acc0[16], acc1[16];
    #pragma unroll
    for (int i = 0; i < 16; i++){ acc0[i] = 0.f; acc1[i] = 0.f; }

    // ---- main loop over 49 kernel offsets (3-buffer, one barrier per k) ----
    int kj = 0;
    uint32_t koff = 0;
    for (int k = 0; k < K2; k++){
        if (k < K2-1) CP_WAIT(1); else CP_WAIT(0);
        __syncthreads();   // buf k%3 visible to all; buf (k+2)%3 readers (iter k-1) done

        if (k + 2 < K2){
            const char* src = (const char*)g_Wh + (size_t)(k+2)*8192;
            uint32_t dst = sb + OFF_B + ((k+2)%3)*8192;
            cpa16(dst + tid*16,       src + tid*16);
            cpa16(dst + (tid+256)*16, src + (tid+256)*16);
            CP_COMMIT();
        }

        uint32_t bBase = sb + OFF_B + (k%3)*8192;
        uint32_t aA0 = aStat0 + koff;
        uint32_t aA1 = aStat1 + koff;

        // rw scales: pre-packed duplicated f16x2, plain LDS.32
        uint32_t s00 = rwp[p00 + k];
        uint32_t s01 = rwp[p01 + k];
        uint32_t s10 = rwp[p10 + k];
        uint32_t s11 = rwp[p11 + k];

        // fragment double-buffer across kc: load kc+1 while computing kc
        uint32_t aF[2][8], bF[2][8];
        ldsm4(&aF[0][0], aA0);
        ldsm4(&aF[0][4], aA1);
        ldsm4(&bF[0][0], bBase + bOff0 + (bhalf16 ^ bXor0));
        ldsm4(&bF[0][4], bBase + bOff1 + (bhalf16 ^ bXor1));

        #pragma unroll
        for (int kc = 0; kc < 4; kc++){
            int cb = kc & 1, nb = cb ^ 1;
            if (kc < 3){
                uint32_t off = (uint32_t)((kc+1)*32);
                ldsm4(&aF[nb][0], aA0 + off);
                ldsm4(&aF[nb][4], aA1 + off);
                uint32_t csw = off + bhalf16;
                ldsm4(&bF[nb][0], bBase + bOff0 + (csw ^ bXor0));
                ldsm4(&bF[nb][4], bBase + bOff1 + (csw ^ bXor1));
            }
            // fold rw into A: regs 0,2 = row l/4 (lo); regs 1,3 = row l/4+8 (hi)
            hmul2(aF[cb][0], s00); hmul2(aF[cb][2], s00);
            hmul2(aF[cb][1], s01); hmul2(aF[cb][3], s01);
            hmul2(aF[cb][4], s10); hmul2(aF[cb][6], s10);
            hmul2(aF[cb][5], s11); hmul2(aF[cb][7], s11);

            mma16816(&acc0[0],  &aF[cb][0], &bF[cb][0]);
            mma16816(&acc0[4],  &aF[cb][0], &bF[cb][2]);
            mma16816(&acc0[8],  &aF[cb][0], &bF[cb][4]);
            mma16816(&acc0[12], &aF[cb][0], &bF[cb][6]);
            mma16816(&acc1[0],  &aF[cb][4], &bF[cb][0]);
            mma16816(&acc1[4],  &aF[cb][4], &bF[cb][2]);
            mma16816(&acc1[8],  &aF[cb][4], &bF[cb][4]);
            mma16816(&acc1[12], &aF[cb][4], &bF[cb][6]);
        }

        // advance k -> k+1 offset without division
        kj++; koff += HROW;
        if (kj == KS){ kj = 0; koff += (uint32_t)((XC - KS)*HROW); }
    }

    // ---- store ----
    #pragma unroll
    for (int tt = 0; tt < 2; tt++){
        float* a = tt ? acc1 : acc0;
        int gh = gh0 + mi*2 + tt;
        int gwl = gw0 + w_lo;
        int gwh = gwl + 8;
        #pragma unroll
        for (int g = 0; g < 4; g++){
            int o = ni*32 + g*8 + 2*(l & 3);
            float b0 = b_lin[o], b1 = b_lin[o+1];
            out[((size_t)(t*C_ + o  )*H_ + gh)*W_ + gwl] = a[g*4 + 0] + b0;
            out[((size_t)(t*C_ + o+1)*H_ + gh)*W_ + gwl] = a[g*4 + 1] + b1;
            out[((size_t)(t*C_ + o  )*H_ + gh)*W_ + gwh] = a[g*4 + 2] + b0;
            out[((size_t)(t*C_ + o+1)*H_ + gh)*W_ + gwh] = a[g*4 + 3] + b1;
        }
    }
}

// ========================= launch =========================

extern "C" void kernel_launch(void* const* d_in, const int* in_sizes, int n_in,
                              void* d_out, int out_size)
{
    const float* x       = (const float*)d_in[0];
    const int*   spix    = (const int*)  d_in[1];
    const float* W       = (const float*)d_in[2];
    const float* b_lin   = (const float*)d_in[3];
    const float* w_scale = (const float*)d_in[4];
    const float* b_scale = (const float*)d_in[5];
    float* out = (float*)d_out;

    cudaFuncSetAttribute(pwd_kernel,  cudaFuncAttributeMaxDynamicSharedMemorySize, PWD_SMEM);
    cudaFuncSetAttribute(main_kernel, cudaFuncAttributeMaxDynamicSharedMemorySize, SMEM_MAIN);

    prep_kernel  <<<C_ + (T_*NSPIX*C_ + 255)/256, 256>>>(W);
    accum_kernel <<<(T_*H_*W_ + 7)/8, 256>>>(x, spix);
    pwd_kernel   <<<T_*49, 256, PWD_SMEM>>>();

    dim3 grid(W_/TW, H_/TH, T_);
    main_kernel<<<grid, 256, SMEM_MAIN>>>(x, spix, b_lin, w_scale, b_scale, out);
}